// round 5
// baseline (speedup 1.0000x reference)
#include <cuda_runtime.h>
#include <cuda_bf16.h>
#include <cstdint>

#define N_NODES  100000
#define N_EDGES  1600000
#define CH       128
#define OUTC     64
#define N_GRAPHS 256
#define BM       64          // rows per GEMM block

// ---------------- scratch (alloc-free rule: __device__ globals) ----------------
__device__ __align__(16) float g_agg[(size_t)N_NODES * CH];
__device__ __align__(16) float g_h  [(size_t)N_NODES * CH];
__device__ __align__(16) float g_pool[N_GRAPHS * CH];
__device__ float g_cnt[N_GRAPHS];
__device__ int   g_idx64;   // 1 if index buffers are int64, 0 if int32

// ---------------- index helpers ----------------
__device__ __forceinline__ long long load_idx(const void* buf, long long i, int is64) {
    if (is64) return ((const long long*)buf)[i];
    return (long long)((const int*)buf)[i];
}

// Detect index dtype: for int64 (values < 2^31) every odd 32-bit word is 0.
__global__ void detect_kernel(const int* __restrict__ ei_raw) {
    int nz = 0;
#pragma unroll 8
    for (int i = 0; i < 1024; i++) nz |= ei_raw[2 * i + 1];
    g_idx64 = (nz == 0) ? 1 : 0;
}

// ---------------- kernels ----------------

// agg <- src (vectorized copy)
__global__ void copy_kernel(const float4* __restrict__ src, float4* __restrict__ dst, int n4) {
    int i = blockIdx.x * blockDim.x + threadIdx.x;
    if (i < n4) dst[i] = src[i];
}

// one warp per edge: gather X[src] row, vector-reduce into g_agg[dst]
__global__ void scatter_kernel(const float* __restrict__ X, const void* __restrict__ ei) {
    int w = (blockIdx.x * blockDim.x + threadIdx.x) >> 5;
    if (w >= N_EDGES) return;
    int lane = threadIdx.x & 31;
    int is64 = g_idx64;                       // uniform branch
    long long s = load_idx(ei, w, is64);            // src node
    long long d = load_idx(ei, (long long)N_EDGES + w, is64);  // dst node
    float4 v = __ldg(reinterpret_cast<const float4*>(X + (size_t)s * CH) + lane);
    float* p = g_agg + (size_t)d * CH + lane * 4;
    asm volatile("red.global.add.v4.f32 [%0], {%1,%2,%3,%4};"
                 :: "l"(p), "f"(v.x), "f"(v.y), "f"(v.z), "f"(v.w) : "memory");
}

// H[r,:] = relu(A[r,:] @ W + b), W is [CH, CH] row-major (k-major rows)
__global__ void gemm_relu_kernel(const float* __restrict__ A, const float* __restrict__ W,
                                 const float* __restrict__ bias, float* __restrict__ H, int M) {
    extern __shared__ float sm[];
    float* Ws = sm;                 // CH*CH
    float* As = Ws + CH * CH;       // BM*CH
    float* bs = As + BM * CH;       // CH
    int tid = threadIdx.x;          // 256 threads

    for (int i = tid; i < CH * CH / 4; i += 256)
        reinterpret_cast<float4*>(Ws)[i] = reinterpret_cast<const float4*>(W)[i];
    if (tid < CH) bs[tid] = bias[tid];

    int row0 = blockIdx.x * BM;
    int rows = min(BM, M - row0);
    for (int i = tid; i < rows * (CH / 4); i += 256)
        reinterpret_cast<float4*>(As)[i] =
            reinterpret_cast<const float4*>(A + (size_t)row0 * CH)[i];
    __syncthreads();

    int cg = tid & 31;   // column group: 4 cols
    int rg = tid >> 5;   // row group: 8 rows (uniform within warp -> LDS broadcast)
    float acc[8][4];
#pragma unroll
    for (int r = 0; r < 8; r++) { acc[r][0]=0.f; acc[r][1]=0.f; acc[r][2]=0.f; acc[r][3]=0.f; }

#pragma unroll 4
    for (int k = 0; k < CH; k++) {
        float4 w4 = reinterpret_cast<float4*>(Ws + k * CH)[cg];
#pragma unroll
        for (int r = 0; r < 8; r++) {
            float a = As[(rg * 8 + r) * CH + k];
            acc[r][0] = fmaf(a, w4.x, acc[r][0]);
            acc[r][1] = fmaf(a, w4.y, acc[r][1]);
            acc[r][2] = fmaf(a, w4.z, acc[r][2]);
            acc[r][3] = fmaf(a, w4.w, acc[r][3]);
        }
    }

    float4 b4 = reinterpret_cast<float4*>(bs)[cg];
#pragma unroll
    for (int r = 0; r < 8; r++) {
        int row = row0 + rg * 8 + r;
        if (row < M) {
            float4 o;
            o.x = fmaxf(acc[r][0] + b4.x, 0.f);
            o.y = fmaxf(acc[r][1] + b4.y, 0.f);
            o.z = fmaxf(acc[r][2] + b4.z, 0.f);
            o.w = fmaxf(acc[r][3] + b4.w, 0.f);
            reinterpret_cast<float4*>(H + (size_t)row * CH)[cg] = o;
        }
    }
}

__global__ void zero_pool_kernel() {
    int i = blockIdx.x * blockDim.x + threadIdx.x;
    if (i < N_GRAPHS * CH) g_pool[i] = 0.f;
}

// counts via binary search over sorted batch (deterministic, contention-free)
__global__ void counts_kernel(const void* __restrict__ batch) {
    int g = blockIdx.x * blockDim.x + threadIdx.x;
    if (g >= N_GRAPHS) return;
    int is64 = g_idx64;
    int lo = 0, hi = N_NODES;
    while (lo < hi) { int m = (lo + hi) >> 1; if (load_idx(batch, m, is64) < g) lo = m + 1; else hi = m; }
    int lb = lo;
    lo = 0; hi = N_NODES;
    while (lo < hi) { int m = (lo + hi) >> 1; if (load_idx(batch, m, is64) <= g) lo = m + 1; else hi = m; }
    g_cnt[g] = (float)(lo - lb);
}

// segment-sum over sorted batch: block handles 128 nodes, thread = channel,
// flush partial sum on graph-id change (few atomics per block)
__global__ void pool_kernel(const float* __restrict__ Hm, const void* __restrict__ batch) {
    int c = threadIdx.x;  // 0..127
    int start = blockIdx.x * 128;
    int end = min(start + 128, N_NODES);
    if (start >= N_NODES) return;
    int is64 = g_idx64;
    long long cur = load_idx(batch, start, is64);
    float sum = 0.f;
    for (int i = start; i < end; i++) {
        long long g = load_idx(batch, i, is64);
        if (g != cur) {
            atomicAdd(&g_pool[(int)cur * CH + c], sum);
            sum = 0.f; cur = g;
        }
        sum += Hm[(size_t)i * CH + c];
    }
    atomicAdd(&g_pool[(int)cur * CH + c], sum);
}

// logits[g,o] = (pool_sum[g,:]/max(cnt,1)) @ Wf + bf
__global__ void final_kernel(const float* __restrict__ Wf, const float* __restrict__ bf,
                             float* __restrict__ out) {
    int g = blockIdx.x;
    int o = threadIdx.x;  // 0..63
    float inv = 1.f / fmaxf(g_cnt[g], 1.f);
    float s = 0.f;
#pragma unroll 8
    for (int k = 0; k < CH; k++)
        s = fmaf(g_pool[g * CH + k], __ldg(&Wf[k * OUTC + o]), s);
    out[g * OUTC + o] = s * inv + bf[o];
}

// ---------------- launch ----------------
extern "C" void kernel_launch(void* const* d_in, const int* in_sizes, int n_in,
                              void* d_out, int out_size) {
    // Identify inputs by element count (robust to metadata ordering).
    // Unique sizes: x=12.8M, edge_index=3.2M, batch=100K, Wf=8192, bf=64.
    // Same-size groups keep relative order: W1,W2,W3 (16384), b1,b2,b3 (128).
    const float* x = nullptr;
    const void* ei = nullptr;
    const void* batch = nullptr;
    const float* Wm[3] = {nullptr, nullptr, nullptr};
    const float* Bv[3] = {nullptr, nullptr, nullptr};
    const float* Wf = nullptr;
    const float* bf = nullptr;
    int wi = 0, bi = 0;
    for (int i = 0; i < n_in; i++) {
        switch (in_sizes[i]) {
            case N_NODES * CH:      x     = (const float*)d_in[i]; break;
            case 2 * N_EDGES:       ei    = d_in[i]; break;
            case N_NODES:           batch = d_in[i]; break;
            case CH * CH:           if (wi < 3) Wm[wi++] = (const float*)d_in[i]; break;
            case CH:                if (bi < 3) Bv[bi++] = (const float*)d_in[i]; break;
            case CH * OUTC:         Wf    = (const float*)d_in[i]; break;
            case OUTC:              bf    = (const float*)d_in[i]; break;
            default: break;
        }
    }
    float* out = (float*)d_out;

    size_t smem = (size_t)(CH * CH + BM * CH + CH) * sizeof(float);
    cudaFuncSetAttribute(gemm_relu_kernel, cudaFuncAttributeMaxDynamicSharedMemorySize, (int)smem);

    float* agg_p; cudaGetSymbolAddress((void**)&agg_p, g_agg);
    float* h_p;   cudaGetSymbolAddress((void**)&h_p,   g_h);

    const int n4 = N_NODES * CH / 4;
    const int copy_blocks = (n4 + 255) / 256;
    const int scat_blocks = (N_EDGES * 32 + 255) / 256;
    const int gemm_blocks = (N_NODES + BM - 1) / BM;

    // ---- dtype detection (int32 vs int64 indices)
    detect_kernel<<<1, 1>>>((const int*)ei);

    // ---- layer 1: agg = x + scatter(x); h = relu(agg @ W1 + b1)
    copy_kernel<<<copy_blocks, 256>>>((const float4*)x, (float4*)agg_p, n4);
    scatter_kernel<<<scat_blocks, 256>>>(x, ei);
    gemm_relu_kernel<<<gemm_blocks, 256, smem>>>(agg_p, Wm[0], Bv[0], h_p, N_NODES);

    // ---- layer 2
    copy_kernel<<<copy_blocks, 256>>>((const float4*)h_p, (float4*)agg_p, n4);
    scatter_kernel<<<scat_blocks, 256>>>(h_p, ei);
    gemm_relu_kernel<<<gemm_blocks, 256, smem>>>(agg_p, Wm[1], Bv[1], h_p, N_NODES);

    // ---- layer 3
    copy_kernel<<<copy_blocks, 256>>>((const float4*)h_p, (float4*)agg_p, n4);
    scatter_kernel<<<scat_blocks, 256>>>(h_p, ei);
    gemm_relu_kernel<<<gemm_blocks, 256, smem>>>(agg_p, Wm[2], Bv[2], h_p, N_NODES);

    // ---- pooling + classifier
    zero_pool_kernel<<<(N_GRAPHS * CH + 255) / 256, 256>>>();
    counts_kernel<<<1, N_GRAPHS>>>(batch);
    pool_kernel<<<(N_NODES + 127) / 128, 128>>>(h_p, batch);
    final_kernel<<<N_GRAPHS, OUTC>>>(Wf, bf, out);

    (void)n_in; (void)out_size;
}

// round 7
// speedup vs baseline: 1.7192x; 1.7192x over previous
#include <cuda_runtime.h>
#include <cuda_bf16.h>
#include <cstdint>

#define N_NODES  100000
#define N_EDGES  1600000
#define CH       128
#define OUTC     64
#define N_GRAPHS 256
#define BM       64          // rows per GEMM block
#define SCAN_BLK 1024
#define SCAN_NB  ((N_NODES + SCAN_BLK - 1) / SCAN_BLK)   // 98

// ---------------- scratch (alloc-free rule: __device__ globals) ----------------
__device__ __align__(16) float g_agg[(size_t)N_NODES * CH];
__device__ __align__(16) float g_h  [(size_t)N_NODES * CH];
__device__ __align__(16) float g_pool[N_GRAPHS * CH];
__device__ float g_cnt[N_GRAPHS];
__device__ int   g_idx64;                 // 1 if index buffers are int64
__device__ int   g_deg[N_NODES];
__device__ int   g_rowptr[N_NODES + 1];
__device__ int   g_cursor[N_NODES];
__device__ int   g_esrc[N_EDGES];
__device__ int   g_blocksum[SCAN_NB];

// ---------------- index helpers ----------------
__device__ __forceinline__ long long load_idx(const void* buf, long long i, int is64) {
    if (is64) return ((const long long*)buf)[i];
    return (long long)((const int*)buf)[i];
}

// Detect index dtype: for int64 (values < 2^31) every odd 32-bit word is 0.
__global__ void detect_kernel(const int* __restrict__ ei_raw) {
    int nz = 0;
#pragma unroll 8
    for (int i = 0; i < 1024; i++) nz |= ei_raw[2 * i + 1];
    g_idx64 = (nz == 0) ? 1 : 0;
}

// ---------------- CSR build ----------------
__global__ void zero_deg_kernel() {
    int i = blockIdx.x * blockDim.x + threadIdx.x;
    if (i < N_NODES) g_deg[i] = 0;
}

__global__ void hist_kernel(const void* __restrict__ ei) {
    int e = blockIdx.x * blockDim.x + threadIdx.x;
    if (e >= N_EDGES) return;
    int d = (int)load_idx(ei, (long long)N_EDGES + e, g_idx64);
    atomicAdd(&g_deg[d], 1);
}

// per-block exclusive scan of deg -> rowptr, block totals -> blocksum
__global__ void scan1_kernel() {
    __shared__ int sm[SCAN_BLK];
    int i = blockIdx.x * SCAN_BLK + threadIdx.x;
    int v = (i < N_NODES) ? g_deg[i] : 0;
    sm[threadIdx.x] = v;
    __syncthreads();
    for (int off = 1; off < SCAN_BLK; off <<= 1) {
        int t = (threadIdx.x >= off) ? sm[threadIdx.x - off] : 0;
        __syncthreads();
        sm[threadIdx.x] += t;
        __syncthreads();
    }
    if (i < N_NODES) g_rowptr[i] = sm[threadIdx.x] - v;   // exclusive
    if (threadIdx.x == SCAN_BLK - 1) g_blocksum[blockIdx.x] = sm[SCAN_BLK - 1];
}

__global__ void scan2_kernel() {
    if (threadIdx.x != 0) return;
    int run = 0;
    for (int b = 0; b < SCAN_NB; b++) { int t = g_blocksum[b]; g_blocksum[b] = run; run += t; }
    g_rowptr[N_NODES] = N_EDGES;
}

__global__ void scan3_kernel() {
    int i = blockIdx.x * blockDim.x + threadIdx.x;
    if (i >= N_NODES) return;
    int r = g_rowptr[i] + g_blocksum[i >> 10];
    g_rowptr[i] = r;
    g_cursor[i] = r;
}

__global__ void fill_kernel(const void* __restrict__ ei) {
    int e = blockIdx.x * blockDim.x + threadIdx.x;
    if (e >= N_EDGES) return;
    int is64 = g_idx64;
    int s = (int)load_idx(ei, e, is64);
    int d = (int)load_idx(ei, (long long)N_EDGES + e, is64);
    int pos = atomicAdd(&g_cursor[d], 1);
    g_esrc[pos] = s;
}

// ---------------- aggregation: out[n,:] = X[n,:] + sum_{s in N(n)} X[s,:] ----------------
// one warp per node, register accumulation, single write, no atomics
__global__ void aggregate_kernel(const float* __restrict__ X, float* __restrict__ out) {
    int w = (blockIdx.x * blockDim.x + threadIdx.x) >> 5;
    if (w >= N_NODES) return;
    int lane = threadIdx.x & 31;
    int beg = __ldg(&g_rowptr[w]);
    int end = __ldg(&g_rowptr[w + 1]);
    float4 acc = __ldg(reinterpret_cast<const float4*>(X + (size_t)w * CH) + lane);
    int e = beg;
    for (; e + 1 < end; e += 2) {           // 2-way unroll for MLP
        int s0 = __ldg(&g_esrc[e]);
        int s1 = __ldg(&g_esrc[e + 1]);
        float4 v0 = __ldg(reinterpret_cast<const float4*>(X + (size_t)s0 * CH) + lane);
        float4 v1 = __ldg(reinterpret_cast<const float4*>(X + (size_t)s1 * CH) + lane);
        acc.x += v0.x + v1.x; acc.y += v0.y + v1.y;
        acc.z += v0.z + v1.z; acc.w += v0.w + v1.w;
    }
    if (e < end) {
        int s = __ldg(&g_esrc[e]);
        float4 v = __ldg(reinterpret_cast<const float4*>(X + (size_t)s * CH) + lane);
        acc.x += v.x; acc.y += v.y; acc.z += v.z; acc.w += v.w;
    }
    reinterpret_cast<float4*>(out + (size_t)w * CH)[lane] = acc;
}

// ---------------- GEMM: H[r,:] = relu(A[r,:] @ W + b) ----------------
__global__ void gemm_relu_kernel(const float* __restrict__ A, const float* __restrict__ W,
                                 const float* __restrict__ bias, float* __restrict__ H, int M) {
    extern __shared__ float sm[];
    float* Ws = sm;                 // CH*CH
    float* As = Ws + CH * CH;       // BM*CH
    float* bs = As + BM * CH;       // CH
    int tid = threadIdx.x;          // 256 threads

    for (int i = tid; i < CH * CH / 4; i += 256)
        reinterpret_cast<float4*>(Ws)[i] = reinterpret_cast<const float4*>(W)[i];
    if (tid < CH) bs[tid] = bias[tid];

    int row0 = blockIdx.x * BM;
    int rows = min(BM, M - row0);
    for (int i = tid; i < rows * (CH / 4); i += 256)
        reinterpret_cast<float4*>(As)[i] =
            reinterpret_cast<const float4*>(A + (size_t)row0 * CH)[i];
    __syncthreads();

    int cg = tid & 31;   // column group: 4 cols
    int rg = tid >> 5;   // row group: 8 rows
    float acc[8][4];
#pragma unroll
    for (int r = 0; r < 8; r++) { acc[r][0]=0.f; acc[r][1]=0.f; acc[r][2]=0.f; acc[r][3]=0.f; }

#pragma unroll 4
    for (int k = 0; k < CH; k++) {
        float4 w4 = reinterpret_cast<float4*>(Ws + k * CH)[cg];
#pragma unroll
        for (int r = 0; r < 8; r++) {
            float a = As[(rg * 8 + r) * CH + k];
            acc[r][0] = fmaf(a, w4.x, acc[r][0]);
            acc[r][1] = fmaf(a, w4.y, acc[r][1]);
            acc[r][2] = fmaf(a, w4.z, acc[r][2]);
            acc[r][3] = fmaf(a, w4.w, acc[r][3]);
        }
    }

    float4 b4 = reinterpret_cast<float4*>(bs)[cg];
#pragma unroll
    for (int r = 0; r < 8; r++) {
        int row = row0 + rg * 8 + r;
        if (row < M) {
            float4 o;
            o.x = fmaxf(acc[r][0] + b4.x, 0.f);
            o.y = fmaxf(acc[r][1] + b4.y, 0.f);
            o.z = fmaxf(acc[r][2] + b4.z, 0.f);
            o.w = fmaxf(acc[r][3] + b4.w, 0.f);
            reinterpret_cast<float4*>(H + (size_t)row * CH)[cg] = o;
        }
    }
}

// ---------------- pooling + classifier ----------------
__global__ void zero_pool_kernel() {
    int i = blockIdx.x * blockDim.x + threadIdx.x;
    if (i < N_GRAPHS * CH) g_pool[i] = 0.f;
}

__global__ void counts_kernel(const void* __restrict__ batch) {
    int g = blockIdx.x * blockDim.x + threadIdx.x;
    if (g >= N_GRAPHS) return;
    int is64 = g_idx64;
    int lo = 0, hi = N_NODES;
    while (lo < hi) { int m = (lo + hi) >> 1; if (load_idx(batch, m, is64) < g) lo = m + 1; else hi = m; }
    int lb = lo;
    lo = 0; hi = N_NODES;
    while (lo < hi) { int m = (lo + hi) >> 1; if (load_idx(batch, m, is64) <= g) lo = m + 1; else hi = m; }
    g_cnt[g] = (float)(lo - lb);
}

__global__ void pool_kernel(const float* __restrict__ Hm, const void* __restrict__ batch) {
    int c = threadIdx.x;  // 0..127
    int start = blockIdx.x * 128;
    int end = min(start + 128, N_NODES);
    if (start >= N_NODES) return;
    int is64 = g_idx64;
    long long cur = load_idx(batch, start, is64);
    float sum = 0.f;
    for (int i = start; i < end; i++) {
        long long g = load_idx(batch, i, is64);
        if (g != cur) {
            atomicAdd(&g_pool[(int)cur * CH + c], sum);
            sum = 0.f; cur = g;
        }
        sum += Hm[(size_t)i * CH + c];
    }
    atomicAdd(&g_pool[(int)cur * CH + c], sum);
}

__global__ void final_kernel(const float* __restrict__ Wf, const float* __restrict__ bf,
                             float* __restrict__ out) {
    int g = blockIdx.x;
    int o = threadIdx.x;  // 0..63
    float inv = 1.f / fmaxf(g_cnt[g], 1.f);
    float s = 0.f;
#pragma unroll 8
    for (int k = 0; k < CH; k++)
        s = fmaf(g_pool[g * CH + k], __ldg(&Wf[k * OUTC + o]), s);
    out[g * OUTC + o] = s * inv + bf[o];
}

// ---------------- launch ----------------
extern "C" void kernel_launch(void* const* d_in, const int* in_sizes, int n_in,
                              void* d_out, int out_size) {
    // Identify inputs by element count (robust to ordering); same-size groups keep order.
    const float* x = nullptr;
    const void* ei = nullptr;
    const void* batch = nullptr;
    const float* Wm[3] = {nullptr, nullptr, nullptr};
    const float* Bv[3] = {nullptr, nullptr, nullptr};
    const float* Wf = nullptr;
    const float* bf = nullptr;
    int wi = 0, bi = 0;
    for (int i = 0; i < n_in; i++) {
        switch (in_sizes[i]) {
            case N_NODES * CH:      x     = (const float*)d_in[i]; break;
            case 2 * N_EDGES:       ei    = d_in[i]; break;
            case N_NODES:           batch = d_in[i]; break;
            case CH * CH:           if (wi < 3) Wm[wi++] = (const float*)d_in[i]; break;
            case CH:                if (bi < 3) Bv[bi++] = (const float*)d_in[i]; break;
            case CH * OUTC:         Wf    = (const float*)d_in[i]; break;
            case OUTC:              bf    = (const float*)d_in[i]; break;
            default: break;
        }
    }
    float* out = (float*)d_out;

    size_t smem = (size_t)(CH * CH + BM * CH + CH) * sizeof(float);
    cudaFuncSetAttribute(gemm_relu_kernel, cudaFuncAttributeMaxDynamicSharedMemorySize, (int)smem);

    float* agg_p; cudaGetSymbolAddress((void**)&agg_p, g_agg);
    float* h_p;   cudaGetSymbolAddress((void**)&h_p,   g_h);

    const int node_blocks = (N_NODES + 255) / 256;
    const int edge_blocks = (N_EDGES + 255) / 256;
    const int agg_blocks  = (N_NODES * 32 + 255) / 256;
    const int gemm_blocks = (N_NODES + BM - 1) / BM;

    // ---- dtype detection + CSR build (once per launch)
    detect_kernel<<<1, 1>>>((const int*)ei);
    zero_deg_kernel<<<node_blocks, 256>>>();
    hist_kernel<<<edge_blocks, 256>>>(ei);
    scan1_kernel<<<SCAN_NB, SCAN_BLK>>>();
    scan2_kernel<<<1, 32>>>();
    scan3_kernel<<<node_blocks, 256>>>();
    fill_kernel<<<edge_blocks, 256>>>(ei);

    // ---- layer 1: agg = x + gather-sum; h = relu(agg @ W1 + b1)
    aggregate_kernel<<<agg_blocks, 256>>>(x, agg_p);
    gemm_relu_kernel<<<gemm_blocks, 256, smem>>>(agg_p, Wm[0], Bv[0], h_p, N_NODES);

    // ---- layer 2
    aggregate_kernel<<<agg_blocks, 256>>>(h_p, agg_p);
    gemm_relu_kernel<<<gemm_blocks, 256, smem>>>(agg_p, Wm[1], Bv[1], h_p, N_NODES);

    // ---- layer 3
    aggregate_kernel<<<agg_blocks, 256>>>(h_p, agg_p);
    gemm_relu_kernel<<<gemm_blocks, 256, smem>>>(agg_p, Wm[2], Bv[2], h_p, N_NODES);

    // ---- pooling + classifier
    zero_pool_kernel<<<(N_GRAPHS * CH + 255) / 256, 256>>>();
    counts_kernel<<<1, N_GRAPHS>>>(batch);
    pool_kernel<<<(N_NODES + 127) / 128, 128>>>(h_p, batch);
    final_kernel<<<N_GRAPHS, OUTC>>>(Wf, bf, out);

    (void)n_in; (void)out_size;
}

// round 8
// speedup vs baseline: 1.8352x; 1.0675x over previous
#include <cuda_runtime.h>
#include <cuda_bf16.h>
#include <cstdint>

#define N_NODES  100000
#define N_EDGES  1600000
#define CH       128
#define OUTC     64
#define N_GRAPHS 256
#define SCAN_BLK 1024
#define SCAN_NB  ((N_NODES + SCAN_BLK - 1) / SCAN_BLK)   // 98

#define BM2 128          // GEMM block tile M
#define PAD 132          // smem row stride (floats) - conflict-free

// ---------------- scratch (alloc-free rule: __device__ globals) ----------------
__device__ __align__(16) float g_agg[(size_t)N_NODES * CH];
__device__ __align__(16) float g_h  [(size_t)N_NODES * CH];
__device__ __align__(16) float g_pool[N_GRAPHS * CH];
__device__ float g_cnt[N_GRAPHS];
__device__ int   g_idx64;                 // 1 if index buffers are int64
__device__ int   g_deg[N_NODES];
__device__ int   g_rowptr[N_NODES + 1];
__device__ int   g_cursor[N_NODES];
__device__ int   g_esrc[N_EDGES];
__device__ int   g_blocksum[SCAN_NB];

// ---------------- index helpers ----------------
__device__ __forceinline__ long long load_idx(const void* buf, long long i, int is64) {
    if (is64) return ((const long long*)buf)[i];
    return (long long)((const int*)buf)[i];
}

__global__ void detect_kernel(const int* __restrict__ ei_raw) {
    int nz = 0;
#pragma unroll 8
    for (int i = 0; i < 1024; i++) nz |= ei_raw[2 * i + 1];
    g_idx64 = (nz == 0) ? 1 : 0;
}

// ---------------- CSR build ----------------
__global__ void zero_deg_kernel() {
    int i = blockIdx.x * blockDim.x + threadIdx.x;
    if (i < N_NODES) g_deg[i] = 0;
}

__global__ void hist_kernel(const void* __restrict__ ei) {
    int e = blockIdx.x * blockDim.x + threadIdx.x;
    if (e >= N_EDGES) return;
    int d = (int)load_idx(ei, (long long)N_EDGES + e, g_idx64);
    atomicAdd(&g_deg[d], 1);
}

__global__ void scan1_kernel() {
    __shared__ int sm[SCAN_BLK];
    int i = blockIdx.x * SCAN_BLK + threadIdx.x;
    int v = (i < N_NODES) ? g_deg[i] : 0;
    sm[threadIdx.x] = v;
    __syncthreads();
    for (int off = 1; off < SCAN_BLK; off <<= 1) {
        int t = (threadIdx.x >= off) ? sm[threadIdx.x - off] : 0;
        __syncthreads();
        sm[threadIdx.x] += t;
        __syncthreads();
    }
    if (i < N_NODES) g_rowptr[i] = sm[threadIdx.x] - v;   // exclusive
    if (threadIdx.x == SCAN_BLK - 1) g_blocksum[blockIdx.x] = sm[SCAN_BLK - 1];
}

__global__ void scan2_kernel() {
    if (threadIdx.x != 0) return;
    int run = 0;
    for (int b = 0; b < SCAN_NB; b++) { int t = g_blocksum[b]; g_blocksum[b] = run; run += t; }
    g_rowptr[N_NODES] = N_EDGES;
}

__global__ void scan3_kernel() {
    int i = blockIdx.x * blockDim.x + threadIdx.x;
    if (i >= N_NODES) return;
    int r = g_rowptr[i] + g_blocksum[i >> 10];
    g_rowptr[i] = r;
    g_cursor[i] = r;
}

__global__ void fill_kernel(const void* __restrict__ ei) {
    int e = blockIdx.x * blockDim.x + threadIdx.x;
    if (e >= N_EDGES) return;
    int is64 = g_idx64;
    int s = (int)load_idx(ei, e, is64);
    int d = (int)load_idx(ei, (long long)N_EDGES + e, is64);
    int pos = atomicAdd(&g_cursor[d], 1);
    g_esrc[pos] = s;
}

// ---------------- aggregation: out[n,:] = X[n,:] + sum_{s in N(n)} X[s,:] ----------------
__global__ void aggregate_kernel(const float* __restrict__ X, float* __restrict__ out) {
    int w = (blockIdx.x * blockDim.x + threadIdx.x) >> 5;
    if (w >= N_NODES) return;
    int lane = threadIdx.x & 31;
    int beg = __ldg(&g_rowptr[w]);
    int end = __ldg(&g_rowptr[w + 1]);
    float4 acc = __ldg(reinterpret_cast<const float4*>(X + (size_t)w * CH) + lane);
    int e = beg;
    for (; e + 1 < end; e += 2) {
        int s0 = __ldg(&g_esrc[e]);
        int s1 = __ldg(&g_esrc[e + 1]);
        float4 v0 = __ldg(reinterpret_cast<const float4*>(X + (size_t)s0 * CH) + lane);
        float4 v1 = __ldg(reinterpret_cast<const float4*>(X + (size_t)s1 * CH) + lane);
        acc.x += v0.x + v1.x; acc.y += v0.y + v1.y;
        acc.z += v0.z + v1.z; acc.w += v0.w + v1.w;
    }
    if (e < end) {
        int s = __ldg(&g_esrc[e]);
        float4 v = __ldg(reinterpret_cast<const float4*>(X + (size_t)s * CH) + lane);
        acc.x += v.x; acc.y += v.y; acc.z += v.z; acc.w += v.w;
    }
    reinterpret_cast<float4*>(out + (size_t)w * CH)[lane] = acc;
}

// ---------------- tf32 tensor-core GEMM: H = relu(A @ W + b) ----------------
__device__ __forceinline__ uint32_t f2tf32(float v) {
    uint32_t u;
    asm("cvt.rna.tf32.f32 %0, %1;" : "=r"(u) : "f"(v));
    return u;
}

__global__ void gemm_tf32_kernel(const float* __restrict__ A, const float* __restrict__ W,
                                 const float* __restrict__ bias, float* __restrict__ H, int M) {
    extern __shared__ float smf[];
    uint32_t* As = reinterpret_cast<uint32_t*>(smf);          // BM2 * PAD (tf32 bits)
    uint32_t* Wt = As + BM2 * PAD;                             // CH * PAD, Wt[n][k]
    float*    bs = reinterpret_cast<float*>(Wt + CH * PAD);    // CH
    int tid = threadIdx.x;       // 256
    int row0 = blockIdx.x * BM2;

    // W -> Wt transposed + tf32 convert (coalesced gmem read)
    for (int i = tid; i < CH * CH; i += 256) {
        int k = i >> 7, n = i & 127;
        Wt[n * PAD + k] = f2tf32(__ldg(&W[i]));
    }
    if (tid < CH) bs[tid] = bias[tid];

    // A tile -> As (float4 loads, zero-pad OOB rows)
    for (int i = tid; i < BM2 * (CH / 4); i += 256) {
        int r = i >> 5;            // row in tile
        int c4 = (i & 31) << 2;    // col (multiple of 4)
        float4 v = make_float4(0.f, 0.f, 0.f, 0.f);
        if (row0 + r < M)
            v = __ldg(reinterpret_cast<const float4*>(A + (size_t)(row0 + r) * CH + c4));
        As[r * PAD + c4 + 0] = f2tf32(v.x);
        As[r * PAD + c4 + 1] = f2tf32(v.y);
        As[r * PAD + c4 + 2] = f2tf32(v.z);
        As[r * PAD + c4 + 3] = f2tf32(v.w);
    }
    __syncthreads();

    int lane = tid & 31;
    int w    = tid >> 5;      // 0..7
    int wm   = w & 3;         // 4 warps along M (32 rows each)
    int wn   = w >> 2;        // 2 warps along N (64 cols each)

    float c[2][8][4];
#pragma unroll
    for (int mi = 0; mi < 2; mi++)
#pragma unroll
        for (int ni = 0; ni < 8; ni++)
#pragma unroll
            for (int j = 0; j < 4; j++) c[mi][ni][j] = 0.f;

#pragma unroll
    for (int ks = 0; ks < 16; ks++) {
        int k0 = ks * 8;
        uint32_t a[2][4];
#pragma unroll
        for (int mi = 0; mi < 2; mi++) {
            int r  = wm * 32 + mi * 16 + (lane >> 2);
            int kk = k0 + (lane & 3);
            a[mi][0] = As[r * PAD + kk];
            a[mi][1] = As[(r + 8) * PAD + kk];
            a[mi][2] = As[r * PAD + kk + 4];
            a[mi][3] = As[(r + 8) * PAD + kk + 4];
        }
#pragma unroll
        for (int ni = 0; ni < 8; ni++) {
            int n  = wn * 64 + ni * 8 + (lane >> 2);
            int kk = k0 + (lane & 3);
            uint32_t b0 = Wt[n * PAD + kk];
            uint32_t b1 = Wt[n * PAD + kk + 4];
#pragma unroll
            for (int mi = 0; mi < 2; mi++) {
                asm volatile(
                    "mma.sync.aligned.m16n8k8.row.col.f32.tf32.tf32.f32 "
                    "{%0,%1,%2,%3}, {%4,%5,%6,%7}, {%8,%9}, {%0,%1,%2,%3};"
                    : "+f"(c[mi][ni][0]), "+f"(c[mi][ni][1]),
                      "+f"(c[mi][ni][2]), "+f"(c[mi][ni][3])
                    : "r"(a[mi][0]), "r"(a[mi][1]), "r"(a[mi][2]), "r"(a[mi][3]),
                      "r"(b0), "r"(b1));
            }
        }
    }

    // epilogue: bias + relu, float2 stores
#pragma unroll
    for (int mi = 0; mi < 2; mi++) {
#pragma unroll
        for (int ni = 0; ni < 8; ni++) {
            int col = wn * 64 + ni * 8 + 2 * (lane & 3);
            float bx = bs[col], by = bs[col + 1];
            int r = row0 + wm * 32 + mi * 16 + (lane >> 2);
            if (r < M) {
                float2 o;
                o.x = fmaxf(c[mi][ni][0] + bx, 0.f);
                o.y = fmaxf(c[mi][ni][1] + by, 0.f);
                *reinterpret_cast<float2*>(H + (size_t)r * CH + col) = o;
            }
            if (r + 8 < M) {
                float2 o;
                o.x = fmaxf(c[mi][ni][2] + bx, 0.f);
                o.y = fmaxf(c[mi][ni][3] + by, 0.f);
                *reinterpret_cast<float2*>(H + (size_t)(r + 8) * CH + col) = o;
            }
        }
    }
}

// ---------------- pooling + classifier ----------------
__global__ void zero_pool_kernel() {
    int i = blockIdx.x * blockDim.x + threadIdx.x;
    if (i < N_GRAPHS * CH) g_pool[i] = 0.f;
}

__global__ void counts_kernel(const void* __restrict__ batch) {
    int g = blockIdx.x * blockDim.x + threadIdx.x;
    if (g >= N_GRAPHS) return;
    int is64 = g_idx64;
    int lo = 0, hi = N_NODES;
    while (lo < hi) { int m = (lo + hi) >> 1; if (load_idx(batch, m, is64) < g) lo = m + 1; else hi = m; }
    int lb = lo;
    lo = 0; hi = N_NODES;
    while (lo < hi) { int m = (lo + hi) >> 1; if (load_idx(batch, m, is64) <= g) lo = m + 1; else hi = m; }
    g_cnt[g] = (float)(lo - lb);
}

__global__ void pool_kernel(const float* __restrict__ Hm, const void* __restrict__ batch) {
    int c = threadIdx.x;  // 0..127
    int start = blockIdx.x * 128;
    int end = min(start + 128, N_NODES);
    if (start >= N_NODES) return;
    int is64 = g_idx64;
    long long cur = load_idx(batch, start, is64);
    float sum = 0.f;
    for (int i = start; i < end; i++) {
        long long g = load_idx(batch, i, is64);
        if (g != cur) {
            atomicAdd(&g_pool[(int)cur * CH + c], sum);
            sum = 0.f; cur = g;
        }
        sum += Hm[(size_t)i * CH + c];
    }
    atomicAdd(&g_pool[(int)cur * CH + c], sum);
}

__global__ void final_kernel(const float* __restrict__ Wf, const float* __restrict__ bf,
                             float* __restrict__ out) {
    int g = blockIdx.x;
    int o = threadIdx.x;  // 0..63
    float inv = 1.f / fmaxf(g_cnt[g], 1.f);
    float s = 0.f;
#pragma unroll 8
    for (int k = 0; k < CH; k++)
        s = fmaf(g_pool[g * CH + k], __ldg(&Wf[k * OUTC + o]), s);
    out[g * OUTC + o] = s * inv + bf[o];
}

// ---------------- launch ----------------
extern "C" void kernel_launch(void* const* d_in, const int* in_sizes, int n_in,
                              void* d_out, int out_size) {
    const float* x = nullptr;
    const void* ei = nullptr;
    const void* batch = nullptr;
    const float* Wm[3] = {nullptr, nullptr, nullptr};
    const float* Bv[3] = {nullptr, nullptr, nullptr};
    const float* Wf = nullptr;
    const float* bf = nullptr;
    int wi = 0, bi = 0;
    for (int i = 0; i < n_in; i++) {
        switch (in_sizes[i]) {
            case N_NODES * CH:      x     = (const float*)d_in[i]; break;
            case 2 * N_EDGES:       ei    = d_in[i]; break;
            case N_NODES:           batch = d_in[i]; break;
            case CH * CH:           if (wi < 3) Wm[wi++] = (const float*)d_in[i]; break;
            case CH:                if (bi < 3) Bv[bi++] = (const float*)d_in[i]; break;
            case CH * OUTC:         Wf    = (const float*)d_in[i]; break;
            case OUTC:              bf    = (const float*)d_in[i]; break;
            default: break;
        }
    }
    float* out = (float*)d_out;

    size_t smem = (size_t)(BM2 * PAD + CH * PAD + CH) * sizeof(float);
    cudaFuncSetAttribute(gemm_tf32_kernel, cudaFuncAttributeMaxDynamicSharedMemorySize, (int)smem);

    float* agg_p; cudaGetSymbolAddress((void**)&agg_p, g_agg);
    float* h_p;   cudaGetSymbolAddress((void**)&h_p,   g_h);

    const int node_blocks = (N_NODES + 255) / 256;
    const int edge_blocks = (N_EDGES + 255) / 256;
    const int agg_blocks  = (N_NODES * 32 + 255) / 256;
    const int gemm_blocks = (N_NODES + BM2 - 1) / BM2;

    // ---- dtype detection + CSR build (once per launch)
    detect_kernel<<<1, 1>>>((const int*)ei);
    zero_deg_kernel<<<node_blocks, 256>>>();
    hist_kernel<<<edge_blocks, 256>>>(ei);
    scan1_kernel<<<SCAN_NB, SCAN_BLK>>>();
    scan2_kernel<<<1, 32>>>();
    scan3_kernel<<<node_blocks, 256>>>();
    fill_kernel<<<edge_blocks, 256>>>(ei);

    // ---- layer 1
    aggregate_kernel<<<agg_blocks, 256>>>(x, agg_p);
    gemm_tf32_kernel<<<gemm_blocks, 256, smem>>>(agg_p, Wm[0], Bv[0], h_p, N_NODES);

    // ---- layer 2
    aggregate_kernel<<<agg_blocks, 256>>>(h_p, agg_p);
    gemm_tf32_kernel<<<gemm_blocks, 256, smem>>>(agg_p, Wm[1], Bv[1], h_p, N_NODES);

    // ---- layer 3
    aggregate_kernel<<<agg_blocks, 256>>>(h_p, agg_p);
    gemm_tf32_kernel<<<gemm_blocks, 256, smem>>>(agg_p, Wm[2], Bv[2], h_p, N_NODES);

    // ---- pooling + classifier
    zero_pool_kernel<<<(N_GRAPHS * CH + 255) / 256, 256>>>();
    counts_kernel<<<1, N_GRAPHS>>>(batch);
    pool_kernel<<<(N_NODES + 127) / 128, 128>>>(h_p, batch);
    final_kernel<<<N_GRAPHS, OUTC>>>(Wf, bf, out);

    (void)n_in; (void)out_size;
}

// round 9
// speedup vs baseline: 1.8928x; 1.0314x over previous
#include <cuda_runtime.h>
#include <cuda_bf16.h>
#include <cstdint>

#define N_NODES  100000
#define N_EDGES  1600000
#define CH       128
#define OUTC     64
#define N_GRAPHS 256
#define SCAN_BLK 1024
#define SCAN_NB  ((N_NODES + SCAN_BLK - 1) / SCAN_BLK)   // 98

#define BM2  128          // GEMM block tile M
#define PAD2 136          // smem row stride (u32) - conflict-free paired-k loads
// B-fragment table: [layer][wn][ks][lane][ni][j] = 3*2*16*32*8*2 u32
#define BFRAG_PER_LAYER (2 * 16 * 32 * 8 * 2)

// ---------------- scratch (alloc-free rule: __device__ globals) ----------------
__device__ __align__(16) float g_agg[(size_t)N_NODES * CH];
__device__ __align__(16) float g_h  [(size_t)N_NODES * CH];
__device__ __align__(16) float g_pool[N_GRAPHS * CH];
__device__ float g_cnt[N_GRAPHS];
__device__ int   g_idx64;                 // 1 if index buffers are int64
__device__ int   g_deg[N_NODES];
__device__ int   g_rowptr[N_NODES + 1];
__device__ int   g_cursor[N_NODES];
__device__ int   g_esrc[N_EDGES];
__device__ int   g_blocksum[SCAN_NB];
__device__ __align__(16) uint32_t g_bfrag[3 * BFRAG_PER_LAYER];

// ---------------- index helpers ----------------
__device__ __forceinline__ long long load_idx(const void* buf, long long i, int is64) {
    if (is64) return ((const long long*)buf)[i];
    return (long long)((const int*)buf)[i];
}

__global__ void detect_kernel(const int* __restrict__ ei_raw) {
    int nz = 0;
#pragma unroll 8
    for (int i = 0; i < 1024; i++) nz |= ei_raw[2 * i + 1];
    g_idx64 = (nz == 0) ? 1 : 0;
}

// ---------------- CSR build ----------------
__global__ void zero_deg_kernel() {
    int i = blockIdx.x * blockDim.x + threadIdx.x;
    if (i < N_NODES) g_deg[i] = 0;
}

__global__ void hist_kernel(const void* __restrict__ ei) {
    int e = blockIdx.x * blockDim.x + threadIdx.x;
    if (e >= N_EDGES) return;
    int d = (int)load_idx(ei, (long long)N_EDGES + e, g_idx64);
    atomicAdd(&g_deg[d], 1);
}

__global__ void scan1_kernel() {
    __shared__ int sm[SCAN_BLK];
    int i = blockIdx.x * SCAN_BLK + threadIdx.x;
    int v = (i < N_NODES) ? g_deg[i] : 0;
    sm[threadIdx.x] = v;
    __syncthreads();
    for (int off = 1; off < SCAN_BLK; off <<= 1) {
        int t = (threadIdx.x >= off) ? sm[threadIdx.x - off] : 0;
        __syncthreads();
        sm[threadIdx.x] += t;
        __syncthreads();
    }
    if (i < N_NODES) g_rowptr[i] = sm[threadIdx.x] - v;   // exclusive
    if (threadIdx.x == SCAN_BLK - 1) g_blocksum[blockIdx.x] = sm[SCAN_BLK - 1];
}

__global__ void scan2_kernel() {
    if (threadIdx.x != 0) return;
    int run = 0;
    for (int b = 0; b < SCAN_NB; b++) { int t = g_blocksum[b]; g_blocksum[b] = run; run += t; }
    g_rowptr[N_NODES] = N_EDGES;
}

__global__ void scan3_kernel() {
    int i = blockIdx.x * blockDim.x + threadIdx.x;
    if (i >= N_NODES) return;
    int r = g_rowptr[i] + g_blocksum[i >> 10];
    g_rowptr[i] = r;
    g_cursor[i] = r;
}

__global__ void fill_kernel(const void* __restrict__ ei) {
    int e = blockIdx.x * blockDim.x + threadIdx.x;
    if (e >= N_EDGES) return;
    int is64 = g_idx64;
    int s = (int)load_idx(ei, e, is64);
    int d = (int)load_idx(ei, (long long)N_EDGES + e, is64);
    int pos = atomicAdd(&g_cursor[d], 1);
    g_esrc[pos] = s;
}

// ---------------- aggregation: out[n,:] = X[n,:] + sum_{s in N(n)} X[s,:] ----------------
__global__ void aggregate_kernel(const float* __restrict__ X, float* __restrict__ out) {
    int w = (blockIdx.x * blockDim.x + threadIdx.x) >> 5;
    if (w >= N_NODES) return;
    int lane = threadIdx.x & 31;
    int beg = __ldg(&g_rowptr[w]);
    int end = __ldg(&g_rowptr[w + 1]);
    float4 acc = __ldg(reinterpret_cast<const float4*>(X + (size_t)w * CH) + lane);
    int e = beg;
    for (; e + 1 < end; e += 2) {
        int s0 = __ldg(&g_esrc[e]);
        int s1 = __ldg(&g_esrc[e + 1]);
        float4 v0 = __ldg(reinterpret_cast<const float4*>(X + (size_t)s0 * CH) + lane);
        float4 v1 = __ldg(reinterpret_cast<const float4*>(X + (size_t)s1 * CH) + lane);
        acc.x += v0.x + v1.x; acc.y += v0.y + v1.y;
        acc.z += v0.z + v1.z; acc.w += v0.w + v1.w;
    }
    if (e < end) {
        int s = __ldg(&g_esrc[e]);
        float4 v = __ldg(reinterpret_cast<const float4*>(X + (size_t)s * CH) + lane);
        acc.x += v.x; acc.y += v.y; acc.z += v.z; acc.w += v.w;
    }
    reinterpret_cast<float4*>(out + (size_t)w * CH)[lane] = acc;
}

// ---------------- tf32 helpers ----------------
__device__ __forceinline__ uint32_t f2tf32(float v) {
    uint32_t u;
    asm("cvt.rna.tf32.f32 %0, %1;" : "=r"(u) : "f"(v));
    return u;
}

// Precompute per-layer B fragments in mma register layout (thread-contiguous).
// idx = ((((l*2+wn)*16+ks)*32+lane)*8+ni)*2+j ; value = tf32(W_l[kk*128+n])
// n = wn*64+ni*8+(lane>>2), kk = ks*8+(lane&3)+j*4
__global__ void wfrag_kernel(const float* __restrict__ W0, const float* __restrict__ W1,
                             const float* __restrict__ W2) {
    int idx = blockIdx.x * blockDim.x + threadIdx.x;
    if (idx >= 3 * BFRAG_PER_LAYER) return;
    int j    = idx & 1;
    int ni   = (idx >> 1) & 7;
    int lane = (idx >> 4) & 31;
    int ks   = (idx >> 9) & 15;
    int wn   = (idx >> 13) & 1;
    int l    = idx >> 14;
    int n  = wn * 64 + ni * 8 + (lane >> 2);
    int kk = ks * 8 + (lane & 3) + j * 4;
    const float* W = (l == 0) ? W0 : ((l == 1) ? W1 : W2);
    g_bfrag[idx] = f2tf32(__ldg(&W[kk * CH + n]));
}

// ---------------- tf32 tensor-core GEMM: H = relu(A @ W + b) ----------------
// A tile in smem (paired-k permuted layout), B fragments from L1-resident global.
__global__ __launch_bounds__(256, 3)
void gemm_tf32_kernel(const float* __restrict__ A, const uint4* __restrict__ bfrag4,
                      const float* __restrict__ bias, float* __restrict__ H, int M) {
    extern __shared__ uint32_t As[];     // BM2 * PAD2
    int tid = threadIdx.x;               // 256
    int row0 = blockIdx.x * BM2;

    // A tile -> smem, permuted so (k, k+4) are adjacent:
    // p(k) = (k & ~7) + (k&3)*2 + ((k>>2)&1)
    for (int i = tid; i < BM2 * (CH / 4); i += 256) {
        int r  = i >> 5;
        int c4 = (i & 31) << 2;
        float4 v = make_float4(0.f, 0.f, 0.f, 0.f);
        if (row0 + r < M)
            v = __ldg(reinterpret_cast<const float4*>(A + (size_t)(row0 + r) * CH + c4));
        int base = r * PAD2 + (c4 & ~7) + ((c4 & 4) ? 1 : 0);
        As[base + 0] = f2tf32(v.x);
        As[base + 2] = f2tf32(v.y);
        As[base + 4] = f2tf32(v.z);
        As[base + 6] = f2tf32(v.w);
    }
    __syncthreads();

    int lane = tid & 31;
    int w    = tid >> 5;      // 0..7
    int wm   = w & 3;         // 4 warps along M (32 rows each)
    int wn   = w >> 2;        // 2 warps along N (64 cols each)

    float c[2][8][4];
#pragma unroll
    for (int mi = 0; mi < 2; mi++)
#pragma unroll
        for (int ni = 0; ni < 8; ni++)
#pragma unroll
            for (int j = 0; j < 4; j++) c[mi][ni][j] = 0.f;

    // per-thread B base (uint4 units): ((wn*16+ks)*32 + lane)*4 + q
    const uint4* bwarp = bfrag4 + (wn * 16) * 128 + lane * 4;
    const uint32_t* a_base = As + (wm * 32 + (lane >> 2)) * PAD2 + (lane & 3) * 2;

#pragma unroll
    for (int ks = 0; ks < 16; ks++) {
        // A fragments: LDS.64 pairs (k, k+4)
        uint2 ar0 = *reinterpret_cast<const uint2*>(a_base + ks * 8);              // row,   mi=0
        uint2 ar8 = *reinterpret_cast<const uint2*>(a_base + 8 * PAD2 + ks * 8);   // row+8
        uint2 br0 = *reinterpret_cast<const uint2*>(a_base + 16 * PAD2 + ks * 8);  // mi=1
        uint2 br8 = *reinterpret_cast<const uint2*>(a_base + 24 * PAD2 + ks * 8);
        // B fragments: 4x LDG.128 (L1-resident)
        const uint4* p = bwarp + ks * 128;
#pragma unroll
        for (int q = 0; q < 4; q++) {
            uint4 bv = __ldg(p + q);
            // bv = { (ni=2q,j0), (2q,j1), (2q+1,j0), (2q+1,j1) }
            asm volatile(
                "mma.sync.aligned.m16n8k8.row.col.f32.tf32.tf32.f32 "
                "{%0,%1,%2,%3}, {%4,%5,%6,%7}, {%8,%9}, {%0,%1,%2,%3};"
                : "+f"(c[0][2*q][0]), "+f"(c[0][2*q][1]), "+f"(c[0][2*q][2]), "+f"(c[0][2*q][3])
                : "r"(ar0.x), "r"(ar8.x), "r"(ar0.y), "r"(ar8.y), "r"(bv.x), "r"(bv.y));
            asm volatile(
                "mma.sync.aligned.m16n8k8.row.col.f32.tf32.tf32.f32 "
                "{%0,%1,%2,%3}, {%4,%5,%6,%7}, {%8,%9}, {%0,%1,%2,%3};"
                : "+f"(c[1][2*q][0]), "+f"(c[1][2*q][1]), "+f"(c[1][2*q][2]), "+f"(c[1][2*q][3])
                : "r"(br0.x), "r"(br8.x), "r"(br0.y), "r"(br8.y), "r"(bv.x), "r"(bv.y));
            asm volatile(
                "mma.sync.aligned.m16n8k8.row.col.f32.tf32.tf32.f32 "
                "{%0,%1,%2,%3}, {%4,%5,%6,%7}, {%8,%9}, {%0,%1,%2,%3};"
                : "+f"(c[0][2*q+1][0]), "+f"(c[0][2*q+1][1]), "+f"(c[0][2*q+1][2]), "+f"(c[0][2*q+1][3])
                : "r"(ar0.x), "r"(ar8.x), "r"(ar0.y), "r"(ar8.y), "r"(bv.z), "r"(bv.w));
            asm volatile(
                "mma.sync.aligned.m16n8k8.row.col.f32.tf32.tf32.f32 "
                "{%0,%1,%2,%3}, {%4,%5,%6,%7}, {%8,%9}, {%0,%1,%2,%3};"
                : "+f"(c[1][2*q+1][0]), "+f"(c[1][2*q+1][1]), "+f"(c[1][2*q+1][2]), "+f"(c[1][2*q+1][3])
                : "r"(br0.x), "r"(br8.x), "r"(br0.y), "r"(br8.y), "r"(bv.z), "r"(bv.w));
        }
    }

    // epilogue: bias + relu, float2 stores
#pragma unroll
    for (int mi = 0; mi < 2; mi++) {
#pragma unroll
        for (int ni = 0; ni < 8; ni++) {
            int col = wn * 64 + ni * 8 + 2 * (lane & 3);
            float bx = __ldg(&bias[col]), by = __ldg(&bias[col + 1]);
            int r = row0 + wm * 32 + mi * 16 + (lane >> 2);
            if (r < M) {
                float2 o;
                o.x = fmaxf(c[mi][ni][0] + bx, 0.f);
                o.y = fmaxf(c[mi][ni][1] + by, 0.f);
                *reinterpret_cast<float2*>(H + (size_t)r * CH + col) = o;
            }
            if (r + 8 < M) {
                float2 o;
                o.x = fmaxf(c[mi][ni][2] + bx, 0.f);
                o.y = fmaxf(c[mi][ni][3] + by, 0.f);
                *reinterpret_cast<float2*>(H + (size_t)(r + 8) * CH + col) = o;
            }
        }
    }
}

// ---------------- pooling + classifier ----------------
__global__ void zero_pool_kernel() {
    int i = blockIdx.x * blockDim.x + threadIdx.x;
    if (i < N_GRAPHS * CH) g_pool[i] = 0.f;
}

__global__ void counts_kernel(const void* __restrict__ batch) {
    int g = blockIdx.x * blockDim.x + threadIdx.x;
    if (g >= N_GRAPHS) return;
    int is64 = g_idx64;
    int lo = 0, hi = N_NODES;
    while (lo < hi) { int m = (lo + hi) >> 1; if (load_idx(batch, m, is64) < g) lo = m + 1; else hi = m; }
    int lb = lo;
    lo = 0; hi = N_NODES;
    while (lo < hi) { int m = (lo + hi) >> 1; if (load_idx(batch, m, is64) <= g) lo = m + 1; else hi = m; }
    g_cnt[g] = (float)(lo - lb);
}

__global__ void pool_kernel(const float* __restrict__ Hm, const void* __restrict__ batch) {
    int c = threadIdx.x;  // 0..127
    int start = blockIdx.x * 128;
    int end = min(start + 128, N_NODES);
    if (start >= N_NODES) return;
    int is64 = g_idx64;
    long long cur = load_idx(batch, start, is64);
    float sum = 0.f;
    for (int i = start; i < end; i++) {
        long long g = load_idx(batch, i, is64);
        if (g != cur) {
            atomicAdd(&g_pool[(int)cur * CH + c], sum);
            sum = 0.f; cur = g;
        }
        sum += Hm[(size_t)i * CH + c];
    }
    atomicAdd(&g_pool[(int)cur * CH + c], sum);
}

__global__ void final_kernel(const float* __restrict__ Wf, const float* __restrict__ bf,
                             float* __restrict__ out) {
    int g = blockIdx.x;
    int o = threadIdx.x;  // 0..63
    float inv = 1.f / fmaxf(g_cnt[g], 1.f);
    float s = 0.f;
#pragma unroll 8
    for (int k = 0; k < CH; k++)
        s = fmaf(g_pool[g * CH + k], __ldg(&Wf[k * OUTC + o]), s);
    out[g * OUTC + o] = s * inv + bf[o];
}

// ---------------- launch ----------------
extern "C" void kernel_launch(void* const* d_in, const int* in_sizes, int n_in,
                              void* d_out, int out_size) {
    const float* x = nullptr;
    const void* ei = nullptr;
    const void* batch = nullptr;
    const float* Wm[3] = {nullptr, nullptr, nullptr};
    const float* Bv[3] = {nullptr, nullptr, nullptr};
    const float* Wf = nullptr;
    const float* bf = nullptr;
    int wi = 0, bi = 0;
    for (int i = 0; i < n_in; i++) {
        switch (in_sizes[i]) {
            case N_NODES * CH:      x     = (const float*)d_in[i]; break;
            case 2 * N_EDGES:       ei    = d_in[i]; break;
            case N_NODES:           batch = d_in[i]; break;
            case CH * CH:           if (wi < 3) Wm[wi++] = (const float*)d_in[i]; break;
            case CH:                if (bi < 3) Bv[bi++] = (const float*)d_in[i]; break;
            case CH * OUTC:         Wf    = (const float*)d_in[i]; break;
            case OUTC:              bf    = (const float*)d_in[i]; break;
            default: break;
        }
    }
    float* out = (float*)d_out;

    size_t smem = (size_t)(BM2 * PAD2) * sizeof(uint32_t);   // 69632
    cudaFuncSetAttribute(gemm_tf32_kernel, cudaFuncAttributeMaxDynamicSharedMemorySize, (int)smem);

    float* agg_p; cudaGetSymbolAddress((void**)&agg_p, g_agg);
    float* h_p;   cudaGetSymbolAddress((void**)&h_p,   g_h);
    uint32_t* bfrag_p; cudaGetSymbolAddress((void**)&bfrag_p, g_bfrag);

    const int node_blocks = (N_NODES + 255) / 256;
    const int edge_blocks = (N_EDGES + 255) / 256;
    const int agg_blocks  = (N_NODES * 32 + 255) / 256;
    const int gemm_blocks = (N_NODES + BM2 - 1) / BM2;

    // ---- dtype detection + CSR build + W fragments (once per launch)
    detect_kernel<<<1, 1>>>((const int*)ei);
    zero_deg_kernel<<<node_blocks, 256>>>();
    hist_kernel<<<edge_blocks, 256>>>(ei);
    scan1_kernel<<<SCAN_NB, SCAN_BLK>>>();
    scan2_kernel<<<1, 32>>>();
    scan3_kernel<<<node_blocks, 256>>>();
    fill_kernel<<<edge_blocks, 256>>>(ei);
    wfrag_kernel<<<(3 * BFRAG_PER_LAYER + 255) / 256, 256>>>(Wm[0], Wm[1], Wm[2]);

    // ---- layer 1
    aggregate_kernel<<<agg_blocks, 256>>>(x, agg_p);
    gemm_tf32_kernel<<<gemm_blocks, 256, smem>>>(agg_p, (const uint4*)(bfrag_p), Bv[0], h_p, N_NODES);

    // ---- layer 2
    aggregate_kernel<<<agg_blocks, 256>>>(h_p, agg_p);
    gemm_tf32_kernel<<<gemm_blocks, 256, smem>>>(agg_p, (const uint4*)(bfrag_p + BFRAG_PER_LAYER), Bv[1], h_p, N_NODES);

    // ---- layer 3
    aggregate_kernel<<<agg_blocks, 256>>>(h_p, agg_p);
    gemm_tf32_kernel<<<gemm_blocks, 256, smem>>>(agg_p, (const uint4*)(bfrag_p + 2 * BFRAG_PER_LAYER), Bv[2], h_p, N_NODES);

    // ---- pooling + classifier
    zero_pool_kernel<<<(N_GRAPHS * CH + 255) / 256, 256>>>();
    counts_kernel<<<1, N_GRAPHS>>>(batch);
    pool_kernel<<<(N_NODES + 127) / 128, 128>>>(h_p, batch);
    final_kernel<<<N_GRAPHS, OUTC>>>(Wf, bf, out);

    (void)n_in; (void)out_size;
}

// round 12
// speedup vs baseline: 2.2349x; 1.1807x over previous
#include <cuda_runtime.h>
#include <cuda_fp16.h>
#include <cstdint>

#define N_NODES  100000
#define N_EDGES  1600000
#define CH       128
#define OUTC     64
#define N_GRAPHS 256
#define SCAN_BLK 1024
#define SCAN_NB  ((N_NODES + SCAN_BLK - 1) / SCAN_BLK)   // 98

#define BM2  128          // GEMM block tile M
#define PAD2 72           // smem row stride in u32 (64 half2 + pad), conflict-free
// B-fragment table (fp16): [layer][wn][ks][lane][ni][j] = 3*2*8*32*8*2 u32
#define BFRAG_PER_LAYER (2 * 8 * 32 * 8 * 2)

// ---------------- scratch (alloc-free rule: __device__ globals) ----------------
__device__ __align__(16) __half g_xh [(size_t)N_NODES * CH];   // fp16 copy of x
__device__ __align__(16) __half g_agg[(size_t)N_NODES * CH];   // fp16 agg
__device__ __align__(16) __half g_h  [(size_t)N_NODES * CH];   // fp16 activations
__device__ __align__(16) float g_pool[N_GRAPHS * CH];
__device__ float g_cnt[N_GRAPHS];
__device__ int   g_idx64;
__device__ int   g_deg[N_NODES];
__device__ int   g_rowptr[N_NODES + 1];
__device__ int   g_cursor[N_NODES];
__device__ int   g_esrc[N_EDGES];
__device__ int   g_blocksum[SCAN_NB];
__device__ __align__(16) uint32_t g_bfrag[3 * BFRAG_PER_LAYER];

// ---------------- helpers ----------------
__device__ __forceinline__ long long load_idx(const void* buf, long long i, int is64) {
    if (is64) return ((const long long*)buf)[i];
    return (long long)((const int*)buf)[i];
}

__device__ __forceinline__ float4 h4f(uint2 v) {
    float2 a = __half22float2(*reinterpret_cast<__half2*>(&v.x));
    float2 b = __half22float2(*reinterpret_cast<__half2*>(&v.y));
    return make_float4(a.x, a.y, b.x, b.y);
}
__device__ __forceinline__ uint2 f4h(float4 v) {
    uint2 o;
    __half2 lo = __floats2half2_rn(v.x, v.y);
    __half2 hi = __floats2half2_rn(v.z, v.w);
    o.x = *reinterpret_cast<uint32_t*>(&lo);
    o.y = *reinterpret_cast<uint32_t*>(&hi);
    return o;
}

__global__ void detect_kernel(const int* __restrict__ ei_raw) {
    int nz = 0;
#pragma unroll 8
    for (int i = 0; i < 1024; i++) nz |= ei_raw[2 * i + 1];
    g_idx64 = (nz == 0) ? 1 : 0;
}

// x (fp32) -> g_xh (fp16)
__global__ void xconv_kernel(const float2* __restrict__ x2) {
    int i = blockIdx.x * blockDim.x + threadIdx.x;
    if (i >= N_NODES * CH / 2) return;
    float2 v = __ldg(&x2[i]);
    __half2 h = __floats2half2_rn(v.x, v.y);
    reinterpret_cast<__half2*>(g_xh)[i] = h;
}

// ---------------- CSR build ----------------
__global__ void zero_deg_kernel() {
    int i = blockIdx.x * blockDim.x + threadIdx.x;
    if (i < N_NODES) g_deg[i] = 0;
}

__global__ void hist_kernel(const void* __restrict__ ei) {
    int e = blockIdx.x * blockDim.x + threadIdx.x;
    if (e >= N_EDGES) return;
    int d = (int)load_idx(ei, (long long)N_EDGES + e, g_idx64);
    atomicAdd(&g_deg[d], 1);
}

__global__ void scan1_kernel() {
    __shared__ int sm[SCAN_BLK];
    int i = blockIdx.x * SCAN_BLK + threadIdx.x;
    int v = (i < N_NODES) ? g_deg[i] : 0;
    sm[threadIdx.x] = v;
    __syncthreads();
    for (int off = 1; off < SCAN_BLK; off <<= 1) {
        int t = (threadIdx.x >= off) ? sm[threadIdx.x - off] : 0;
        __syncthreads();
        sm[threadIdx.x] += t;
        __syncthreads();
    }
    if (i < N_NODES) g_rowptr[i] = sm[threadIdx.x] - v;
    if (threadIdx.x == SCAN_BLK - 1) g_blocksum[blockIdx.x] = sm[SCAN_BLK - 1];
}

__global__ void scan2_kernel() {
    if (threadIdx.x != 0) return;
    int run = 0;
    for (int b = 0; b < SCAN_NB; b++) { int t = g_blocksum[b]; g_blocksum[b] = run; run += t; }
    g_rowptr[N_NODES] = N_EDGES;
}

__global__ void scan3_kernel() {
    int i = blockIdx.x * blockDim.x + threadIdx.x;
    if (i >= N_NODES) return;
    int r = g_rowptr[i] + g_blocksum[i >> 10];
    g_rowptr[i] = r;
    g_cursor[i] = r;
}

__global__ void fill_kernel(const void* __restrict__ ei) {
    int e = blockIdx.x * blockDim.x + threadIdx.x;
    if (e >= N_EDGES) return;
    int is64 = g_idx64;
    int s = (int)load_idx(ei, e, is64);
    int d = (int)load_idx(ei, (long long)N_EDGES + e, is64);
    int pos = atomicAdd(&g_cursor[d], 1);
    g_esrc[pos] = s;
}

// ---------------- aggregation (fp16 in, fp32 accum, fp16 out) ----------------
// out[n,:] = X[n,:] + sum_{s in N(n)} X[s,:]; warp per node, lane = 4 channels*2
__global__ void aggregate_kernel(const __half* __restrict__ X, __half* __restrict__ out) {
    int w = (blockIdx.x * blockDim.x + threadIdx.x) >> 5;
    if (w >= N_NODES) return;
    int lane = threadIdx.x & 31;
    int beg = __ldg(&g_rowptr[w]);
    int end = __ldg(&g_rowptr[w + 1]);
    const uint2* Xr = reinterpret_cast<const uint2*>(X);   // 32 uint2 per row
    float4 acc = h4f(__ldg(&Xr[(size_t)w * 32 + lane]));
    int e = beg;
    for (; e + 1 < end; e += 2) {
        int s0 = __ldg(&g_esrc[e]);
        int s1 = __ldg(&g_esrc[e + 1]);
        float4 v0 = h4f(__ldg(&Xr[(size_t)s0 * 32 + lane]));
        float4 v1 = h4f(__ldg(&Xr[(size_t)s1 * 32 + lane]));
        acc.x += v0.x + v1.x; acc.y += v0.y + v1.y;
        acc.z += v0.z + v1.z; acc.w += v0.w + v1.w;
    }
    if (e < end) {
        int s = __ldg(&g_esrc[e]);
        float4 v = h4f(__ldg(&Xr[(size_t)s * 32 + lane]));
        acc.x += v.x; acc.y += v.y; acc.z += v.z; acc.w += v.w;
    }
    reinterpret_cast<uint2*>(out)[(size_t)w * 32 + lane] = f4h(acc);
}

// ---------------- fp16 B-fragment precompute ----------------
// idx = ((((l*2+wn)*8+ks)*32+lane)*8+ni)*2+j
// n = wn*64+ni*8+(lane>>2); k0 = ks*16 + 2*(lane&3) + j*8
// value = half2(W[k0][n], W[k0+1][n])
__global__ void wfrag_kernel(const float* __restrict__ W0, const float* __restrict__ W1,
                             const float* __restrict__ W2) {
    int idx = blockIdx.x * blockDim.x + threadIdx.x;
    if (idx >= 3 * BFRAG_PER_LAYER) return;
    int j    = idx & 1;
    int ni   = (idx >> 1) & 7;
    int lane = (idx >> 4) & 31;
    int ks   = (idx >> 9) & 7;
    int wn   = (idx >> 12) & 1;
    int l    = idx >> 13;
    int n  = wn * 64 + ni * 8 + (lane >> 2);
    int k0 = ks * 16 + 2 * (lane & 3) + j * 8;
    const float* W = (l == 0) ? W0 : ((l == 1) ? W1 : W2);
    __half2 h = __floats2half2_rn(__ldg(&W[k0 * CH + n]), __ldg(&W[(k0 + 1) * CH + n]));
    g_bfrag[idx] = *reinterpret_cast<uint32_t*>(&h);
}

// ---------------- fp16 tensor-core GEMM: H = relu(A @ W + b), all half ----------------
__global__ __launch_bounds__(256, 4)
void gemm_fp16_kernel(const __half* __restrict__ A, const uint4* __restrict__ bfrag4,
                      const float* __restrict__ bias, __half* __restrict__ H, int M) {
    extern __shared__ uint32_t As[];     // BM2 * PAD2 (half2 units, permuted)
    int tid = threadIdx.x;               // 256
    int row0 = blockIdx.x * BM2;

    // A tile -> smem: uint4 = 4 half2; permute half2 index c2 within groups of 8:
    // p(c2) = (c2&~7) + (c2&3)*2 + ((c2>>2)&1)  -> (c2, c2+4) become adjacent
    for (int i = tid; i < BM2 * 16; i += 256) {
        int r  = i >> 4;
        int c4 = (i & 15) << 2;          // half2 base index (multiple of 4)
        uint4 v = make_uint4(0u, 0u, 0u, 0u);
        if (row0 + r < M)
            v = __ldg(reinterpret_cast<const uint4*>(A + (size_t)(row0 + r) * CH) + (i & 15));
        int base = r * PAD2 + (c4 & ~7) + ((c4 & 4) ? 1 : 0);
        As[base + 0] = v.x;
        As[base + 2] = v.y;
        As[base + 4] = v.z;
        As[base + 6] = v.w;
    }
    __syncthreads();

    int lane = tid & 31;
    int w    = tid >> 5;
    int wm   = w & 3;         // 4 warps along M (32 rows each)
    int wn   = w >> 2;        // 2 warps along N (64 cols each)

    float c[2][8][4];
#pragma unroll
    for (int mi = 0; mi < 2; mi++)
#pragma unroll
        for (int ni = 0; ni < 8; ni++)
#pragma unroll
            for (int j = 0; j < 4; j++) c[mi][ni][j] = 0.f;

    const uint4* bwarp = bfrag4 + ((size_t)wn * 8) * 128 + lane * 4;
    const uint32_t* a_base = As + (wm * 32 + (lane >> 2)) * PAD2 + (lane & 3) * 2;

#pragma unroll
    for (int ks = 0; ks < 8; ks++) {
        // LDS.64: .x = half2(k=2m..), .y = half2(k+8)
        uint2 ar0 = *reinterpret_cast<const uint2*>(a_base + ks * 8);
        uint2 ar8 = *reinterpret_cast<const uint2*>(a_base + 8 * PAD2 + ks * 8);
        uint2 br0 = *reinterpret_cast<const uint2*>(a_base + 16 * PAD2 + ks * 8);
        uint2 br8 = *reinterpret_cast<const uint2*>(a_base + 24 * PAD2 + ks * 8);
        const uint4* p = bwarp + ks * 128;
#pragma unroll
        for (int q = 0; q < 4; q++) {
            uint4 bv = __ldg(p + q);
            asm volatile(
                "mma.sync.aligned.m16n8k16.row.col.f32.f16.f16.f32 "
                "{%0,%1,%2,%3}, {%4,%5,%6,%7}, {%8,%9}, {%0,%1,%2,%3};"
                : "+f"(c[0][2*q][0]), "+f"(c[0][2*q][1]), "+f"(c[0][2*q][2]), "+f"(c[0][2*q][3])
                : "r"(ar0.x), "r"(ar8.x), "r"(ar0.y), "r"(ar8.y), "r"(bv.x), "r"(bv.y));
            asm volatile(
                "mma.sync.aligned.m16n8k16.row.col.f32.f16.f16.f32 "
                "{%0,%1,%2,%3}, {%4,%5,%6,%7}, {%8,%9}, {%0,%1,%2,%3};"
                : "+f"(c[1][2*q][0]), "+f"(c[1][2*q][1]), "+f"(c[1][2*q][2]), "+f"(c[1][2*q][3])
                : "r"(br0.x), "r"(br8.x), "r"(br0.y), "r"(br8.y), "r"(bv.x), "r"(bv.y));
            asm volatile(
                "mma.sync.aligned.m16n8k16.row.col.f32.f16.f16.f32 "
                "{%0,%1,%2,%3}, {%4,%5,%6,%7}, {%8,%9}, {%0,%1,%2,%3};"
                : "+f"(c[0][2*q+1][0]), "+f"(c[0][2*q+1][1]), "+f"(c[0][2*q+1][2]), "+f"(c[0][2*q+1][3])
                : "r"(ar0.x), "r"(ar8.x), "r"(ar0.y), "r"(ar8.y), "r"(bv.z), "r"(bv.w));
            asm volatile(
                "mma.sync.aligned.m16n8k16.row.col.f32.f16.f16.f32 "
                "{%0,%1,%2,%3}, {%4,%5,%6,%7}, {%8,%9}, {%0,%1,%2,%3};"
                : "+f"(c[1][2*q+1][0]), "+f"(c[1][2*q+1][1]), "+f"(c[1][2*q+1][2]), "+f"(c[1][2*q+1][3])
                : "r"(br0.x), "r"(br8.x), "r"(br0.y), "r"(br8.y), "r"(bv.z), "r"(bv.w));
        }
    }

    // epilogue: bias + relu -> half2 stores
#pragma unroll
    for (int mi = 0; mi < 2; mi++) {
#pragma unroll
        for (int ni = 0; ni < 8; ni++) {
            int col = wn * 64 + ni * 8 + 2 * (lane & 3);
            float bx = __ldg(&bias[col]), by = __ldg(&bias[col + 1]);
            int r = row0 + wm * 32 + mi * 16 + (lane >> 2);
            if (r < M) {
                __half2 o = __floats2half2_rn(fmaxf(c[mi][ni][0] + bx, 0.f),
                                              fmaxf(c[mi][ni][1] + by, 0.f));
                *reinterpret_cast<__half2*>(H + (size_t)r * CH + col) = o;
            }
            if (r + 8 < M) {
                __half2 o = __floats2half2_rn(fmaxf(c[mi][ni][2] + bx, 0.f),
                                              fmaxf(c[mi][ni][3] + by, 0.f));
                *reinterpret_cast<__half2*>(H + (size_t)(r + 8) * CH + col) = o;
            }
        }
    }
}

// ---------------- pooling + classifier ----------------
__global__ void zero_pool_kernel() {
    int i = blockIdx.x * blockDim.x + threadIdx.x;
    if (i < N_GRAPHS * CH) g_pool[i] = 0.f;
}

__global__ void counts_kernel(const void* __restrict__ batch) {
    int g = blockIdx.x * blockDim.x + threadIdx.x;
    if (g >= N_GRAPHS) return;
    int is64 = g_idx64;
    int lo = 0, hi = N_NODES;
    while (lo < hi) { int m = (lo + hi) >> 1; if (load_idx(batch, m, is64) < g) lo = m + 1; else hi = m; }
    int lb = lo;
    lo = 0; hi = N_NODES;
    while (lo < hi) { int m = (lo + hi) >> 1; if (load_idx(batch, m, is64) <= g) lo = m + 1; else hi = m; }
    g_cnt[g] = (float)(lo - lb);
}

__global__ void pool_kernel(const __half* __restrict__ Hm, const void* __restrict__ batch) {
    int c = threadIdx.x;  // 0..127
    int start = blockIdx.x * 128;
    int end = min(start + 128, N_NODES);
    if (start >= N_NODES) return;
    int is64 = g_idx64;
    long long cur = load_idx(batch, start, is64);
    float sum = 0.f;
    for (int i = start; i < end; i++) {
        long long g = load_idx(batch, i, is64);
        if (g != cur) {
            atomicAdd(&g_pool[(int)cur * CH + c], sum);
            sum = 0.f; cur = g;
        }
        sum += __half2float(Hm[(size_t)i * CH + c]);
    }
    atomicAdd(&g_pool[(int)cur * CH + c], sum);
}

__global__ void final_kernel(const float* __restrict__ Wf, const float* __restrict__ bf,
                             float* __restrict__ out) {
    int g = blockIdx.x;
    int o = threadIdx.x;  // 0..63
    float inv = 1.f / fmaxf(g_cnt[g], 1.f);
    float s = 0.f;
#pragma unroll 8
    for (int k = 0; k < CH; k++)
        s = fmaf(g_pool[g * CH + k], __ldg(&Wf[k * OUTC + o]), s);
    out[g * OUTC + o] = s * inv + bf[o];
}

// ---------------- launch ----------------
extern "C" void kernel_launch(void* const* d_in, const int* in_sizes, int n_in,
                              void* d_out, int out_size) {
    const float* x = nullptr;
    const void* ei = nullptr;
    const void* batch = nullptr;
    const float* Wm[3] = {nullptr, nullptr, nullptr};
    const float* Bv[3] = {nullptr, nullptr, nullptr};
    const float* Wf = nullptr;
    const float* bf = nullptr;
    int wi = 0, bi = 0;
    for (int i = 0; i < n_in; i++) {
        switch (in_sizes[i]) {
            case N_NODES * CH:      x     = (const float*)d_in[i]; break;
            case 2 * N_EDGES:       ei    = d_in[i]; break;
            case N_NODES:           batch = d_in[i]; break;
            case CH * CH:           if (wi < 3) Wm[wi++] = (const float*)d_in[i]; break;
            case CH:                if (bi < 3) Bv[bi++] = (const float*)d_in[i]; break;
            case CH * OUTC:         Wf    = (const float*)d_in[i]; break;
            case OUTC:              bf    = (const float*)d_in[i]; break;
            default: break;
        }
    }
    float* out = (float*)d_out;

    size_t smem = (size_t)(BM2 * PAD2) * sizeof(uint32_t);   // 36864
    cudaFuncSetAttribute(gemm_fp16_kernel, cudaFuncAttributeMaxDynamicSharedMemorySize, (int)smem);

    __half* xh_p;  cudaGetSymbolAddress((void**)&xh_p,  g_xh);
    __half* agg_p; cudaGetSymbolAddress((void**)&agg_p, g_agg);
    __half* h_p;   cudaGetSymbolAddress((void**)&h_p,   g_h);
    uint32_t* bfrag_p; cudaGetSymbolAddress((void**)&bfrag_p, g_bfrag);

    const int node_blocks = (N_NODES + 255) / 256;
    const int edge_blocks = (N_EDGES + 255) / 256;
    const int agg_blocks  = (N_NODES * 32 + 255) / 256;
    const int gemm_blocks = (N_NODES + BM2 - 1) / BM2;

    // ---- once-per-launch prep
    detect_kernel<<<1, 1>>>((const int*)ei);
    xconv_kernel<<<(N_NODES * CH / 2 + 255) / 256, 256>>>((const float2*)x);
    zero_deg_kernel<<<node_blocks, 256>>>();
    hist_kernel<<<edge_blocks, 256>>>(ei);
    scan1_kernel<<<SCAN_NB, SCAN_BLK>>>();
    scan2_kernel<<<1, 32>>>();
    scan3_kernel<<<node_blocks, 256>>>();
    fill_kernel<<<edge_blocks, 256>>>(ei);
    wfrag_kernel<<<(3 * BFRAG_PER_LAYER + 255) / 256, 256>>>(Wm[0], Wm[1], Wm[2]);

    // ---- layer 1
    aggregate_kernel<<<agg_blocks, 256>>>(xh_p, agg_p);
    gemm_fp16_kernel<<<gemm_blocks, 256, smem>>>(agg_p, (const uint4*)(bfrag_p), Bv[0], h_p, N_NODES);

    // ---- layer 2
    aggregate_kernel<<<agg_blocks, 256>>>(h_p, agg_p);
    gemm_fp16_kernel<<<gemm_blocks, 256, smem>>>(agg_p, (const uint4*)(bfrag_p + BFRAG_PER_LAYER), Bv[1], h_p, N_NODES);

    // ---- layer 3
    aggregate_kernel<<<agg_blocks, 256>>>(h_p, agg_p);
    gemm_fp16_kernel<<<gemm_blocks, 256, smem>>>(agg_p, (const uint4*)(bfrag_p + 2 * BFRAG_PER_LAYER), Bv[2], h_p, N_NODES);

    // ---- pooling + classifier
    zero_pool_kernel<<<(N_GRAPHS * CH + 255) / 256, 256>>>();
    counts_kernel<<<1, N_GRAPHS>>>(batch);
    pool_kernel<<<(N_NODES + 127) / 128, 128>>>(h_p, batch);
    final_kernel<<<N_GRAPHS, OUTC>>>(Wf, bf, out);

    (void)n_in; (void)out_size;
}